// round 7
// baseline (speedup 1.0000x reference)
#include <cuda_runtime.h>
#include <math.h>

#define B 8
#define SL 4096
#define D 128
#define NH 8
#define NB 64       // buckets per hash
#define NC 512      // n_chunks = NH * NB
#define BS 64       // bucket/chunk size
#define NSL (NH*SL) // 32768
#define PAD 132     // smem row stride (floats); %32==4 -> conflict-free rows & cols

#define MNEG (-3.402823466e38f)

typedef unsigned long long ull;

// packed 2x fp32 fma (Blackwell f32x2 pipe; PTX-only)
__device__ __forceinline__ void fma2(ull& d, ull a, ull b) {
    asm("fma.rn.f32x2 %0, %1, %2, %0;" : "+l"(d) : "l"(a), "l"(b));
}
__device__ __forceinline__ ull pack2(float lo, float hi) {
    ull r; asm("mov.b64 %0, {%1, %2};" : "=l"(r) : "f"(lo), "f"(hi)); return r;
}
__device__ __forceinline__ float2 unpack2(ull v) {
    float2 r; asm("mov.b64 {%0, %1}, %2;" : "=f"(r.x), "=f"(r.y) : "l"(v)); return r;
}

// ---------------- scratch (device globals; no runtime allocation) ----------
__device__ int   g_buckets[B][NH][SL];   // bucket incl. h*NB offset
__device__ int   g_hist[B][NC];
__device__ int   g_boff[B][NC];
__device__ int   g_sticker[B][NSL];      // sorted tickers
__device__ int   g_undo[B][NSL];         // ticker -> sorted pos
__device__ int   g_loc1[B][NH][SL];
__device__ int   g_loc2[B][NH][SL];
__device__ float g_so[B][NSL][D];        // sorted attention output
__device__ float g_slog[B][NSL];         // sorted lse

// ---------------- kernels --------------------------------------------------
__global__ void k_zero_hist() {
    g_hist[blockIdx.x][threadIdx.x] = 0;
}

// buckets + histogram. grid (SL/256, NH, B), block 256.
__global__ void k_buckets(const float* __restrict__ qk, const float* __restrict__ rot) {
    __shared__ float rs[32 * 32];      // d-tile (32) x n (32)
    __shared__ float qt_[256 * 33];    // tokens x d-tile, stride 33
    int b = blockIdx.z, h = blockIdx.y;
    int tid = threadIdx.x;
    int s0 = blockIdx.x * 256;

    ull acc2[16];
#pragma unroll
    for (int n = 0; n < 16; n++) acc2[n] = 0ull;

    for (int d0 = 0; d0 < 128; d0 += 32) {
        for (int i = tid; i < 32 * 32; i += 256) {
            int dd = i >> 5, nn = i & 31;
            rs[i] = rot[((size_t)(d0 + dd) * NH + h) * 32 + nn];
        }
        for (int i = tid; i < 256 * 32; i += 256) {
            int r = i >> 5, c = i & 31;
            qt_[r * 33 + c] = qk[((size_t)b * SL + s0 + r) * D + d0 + c];
        }
        __syncthreads();
#pragma unroll 4
        for (int dd = 0; dd < 32; dd++) {
            float qv = qt_[tid * 33 + dd];
            ull qq = pack2(qv, qv);
            const ull* r2 = (const ull*)&rs[dd * 32];
#pragma unroll
            for (int n = 0; n < 16; n++) fma2(acc2[n], qq, r2[n]);
        }
        __syncthreads();
    }
    float acc[32];
#pragma unroll
    for (int n = 0; n < 16; n++) {
        float2 p = unpack2(acc2[n]);
        acc[2 * n] = p.x; acc[2 * n + 1] = p.y;
    }
    // argmax over [acc, -acc], first-max-wins (matches jnp.argmax)
    float best = acc[0]; int idx = 0;
#pragma unroll
    for (int n = 1; n < 32; n++) if (acc[n] > best) { best = acc[n]; idx = n; }
#pragma unroll
    for (int n = 0; n < 32; n++) if (-acc[n] > best) { best = -acc[n]; idx = 32 + n; }
    int s = s0 + tid;
    int bucket = idx + h * NB;
    g_buckets[b][h][s] = bucket;
    atomicAdd(&g_hist[b][bucket], 1);
}

// exclusive scan of 512 bins per batch. grid B, block NC. Hillis-Steele.
__global__ void k_prefix() {
    __shared__ int sh[NC];
    int b = blockIdx.x, tid = threadIdx.x;
    int v = g_hist[b][tid];
    sh[tid] = v;
    __syncthreads();
#pragma unroll
    for (int off = 1; off < NC; off <<= 1) {
        int x = (tid >= off) ? sh[tid - off] : 0;
        __syncthreads();
        sh[tid] += x;
        __syncthreads();
    }
    g_boff[b][tid] = sh[tid] - v;   // exclusive
}

// stable counting-sort scatter: 4 warps per bucket, two-pass (count, scatter).
// grid (NC, B), block 128
__global__ void k_scatter() {
    int bk = blockIdx.x, b = blockIdx.y;
    int h = bk >> 6;
    int warp = threadIdx.x >> 5, lane = threadIdx.x & 31;
    const int* bb = &g_buckets[b][h][0];
    int t0 = warp * (SL / 4);

    __shared__ int wc[4];
    int cnt = 0;
    for (int base = 0; base < SL / 4; base += 32) {
        bool m = (bb[t0 + base + lane] == bk);
        cnt += __popc(__ballot_sync(0xffffffffu, m));
    }
    if (lane == 0) wc[warp] = cnt;
    __syncthreads();

    int pos = g_boff[b][bk];
#pragma unroll
    for (int w = 0; w < 4; w++) if (w < warp) pos += wc[w];

    for (int base = 0; base < SL / 4; base += 32) {
        int t = t0 + base + lane;
        bool m = (bb[t] == bk);
        unsigned bal = __ballot_sync(0xffffffffu, m);
        if (m) {
            int r = __popc(bal & ((1u << lane) - 1));
            int j = h * SL + t;
            g_sticker[b][pos + r] = j;
            g_undo[b][j] = pos + r;
        }
        pos += __popc(bal);
    }
}

// duplicate-detection location codes. grid (B*NSL/256), block 256
__global__ void k_loc() {
    int idx = blockIdx.x * 256 + threadIdx.x;
    int b = idx / NSL, r = idx % NSL;
    int h = r >> 12, t = r & (SL - 1);
    int chunk = g_undo[b][r] >> 6;
    int bucket = g_buckets[b][h][t];
    g_loc1[b][h][t] = bucket * NC + chunk;
    g_loc2[b][h][t] = bucket * NC + ((chunk + 1) & (NC - 1));
}

// chunked attention. grid (NC, B), block 1024, dynamic smem.
// 32 warps; warp w owns query rows {w, w+32} in BOTH QK and PV phases.
extern __shared__ float smem[];
__global__ void __launch_bounds__(1024, 1)
k_attn(const float* __restrict__ qk, const float* __restrict__ v) {
    int n = blockIdx.x, b = blockIdx.y;
    int tid = threadIdx.x;
    int warp = tid >> 5, lane = tid & 31;

    float* qs = smem;              // 64*PAD  (q rows; reused as probs)
    float* ks = qs + 64 * PAD;     // 128*PAD (unit-normalized keys)
    float* vs = ks + 128 * PAD;    // 128*PAD
    int* qt = (int*)(vs + 128 * PAD); // 64
    int* qb = qt + 64;                // 64
    int* kt = qb + 64;                // 128
    int* kb = kt + 128;               // 128
    int* ql1 = kb + 128;              // 64*8
    int* kl  = ql1 + 512;             // 128*20 (loc1/loc2 interleaved, padded to 16B)

    int prev = (n + NC - 1) & (NC - 1);

    // ---- batched index loads first (full MLP on the dependent gathers) ----
    int tfk[4], tfq[2];
#pragma unroll
    for (int u = 0; u < 4; u++) {
        int z = warp + 32 * u;
        int p = (z < 64) ? (n * BS + z) : (prev * BS + (z - 64));
        tfk[u] = g_sticker[b][p];
    }
#pragma unroll
    for (int u = 0; u < 2; u++)
        tfq[u] = g_sticker[b][n * BS + warp + 32 * u];

    // ---- kv rows (z<64 current chunk, z>=64 previous chunk) ----
#pragma unroll
    for (int u = 0; u < 4; u++) {
        int z = warp + 32 * u;
        int t = tfk[u] & (SL - 1), h = tfk[u] >> 12;
        const float* src = qk + ((size_t)b * SL + t) * D;
        float4 x = ((const float4*)src)[lane];
        const float* vsrc = v + ((size_t)b * SL + t) * D;
        float4 vv = ((const float4*)vsrc)[lane];
        float ss = x.x * x.x + x.y * x.y + x.z * x.z + x.w * x.w;
#pragma unroll
        for (int o = 16; o > 0; o >>= 1) ss += __shfl_xor_sync(0xffffffffu, ss, o);
        float inv = rsqrtf(fmaxf(ss, 1e-24f));
        ((float4*)(ks + z * PAD))[lane] = make_float4(x.x * inv, x.y * inv, x.z * inv, x.w * inv);
        ((float4*)(vs + z * PAD))[lane] = vv;
        if (lane == 0) { kt[z] = t; kb[z] = g_buckets[b][h][t]; }
        if (lane < 8)       kl[z * 20 + 2 * lane]           = g_loc1[b][lane][t];
        else if (lane < 16) kl[z * 20 + 2 * (lane - 8) + 1] = g_loc2[b][lane - 8][t];
    }
    // ---- q rows ----
#pragma unroll
    for (int u = 0; u < 2; u++) {
        int s = warp + 32 * u;
        int t = tfq[u] & (SL - 1), h = tfq[u] >> 12;
        ((float4*)(qs + s * PAD))[lane] = ((const float4*)(qk + ((size_t)b * SL + t) * D))[lane];
        if (lane == 0) { qt[s] = t; qb[s] = g_buckets[b][h][t]; }
        if (lane < 8) ql1[s * 8 + lane] = g_loc1[b][lane][t];
    }
    __syncthreads();

    // ---- QK^T: 2 rows x 4 z tile, packed f32x2 over even/odd d ----
    ull acc2[2][4];
#pragma unroll
    for (int j = 0; j < 2; j++)
#pragma unroll
        for (int i = 0; i < 4; i++) acc2[j][i] = 0ull;

#pragma unroll 4
    for (int d = 0; d < 128; d += 4) {
        ulonglong2 kx[4];
#pragma unroll
        for (int i = 0; i < 4; i++)
            kx[i] = *(const ulonglong2*)(ks + (lane + 32 * i) * PAD + d);
#pragma unroll
        for (int j = 0; j < 2; j++) {
            ulonglong2 q2 = *(const ulonglong2*)(qs + (warp + 32 * j) * PAD + d);  // broadcast
#pragma unroll
            for (int i = 0; i < 4; i++) {
                fma2(acc2[j][i], q2.x, kx[i].x);
                fma2(acc2[j][i], q2.y, kx[i].y);
            }
        }
    }
    float acc[2][4];
#pragma unroll
    for (int j = 0; j < 2; j++)
#pragma unroll
        for (int i = 0; i < 4; i++) {
            float2 p = unpack2(acc2[j][i]);
            acc[j][i] = p.x + p.y;
        }

    // ---- masks + dup correction (reference order: causal, self, bucket, dup) ----
    int qtv[2], qbv[2], ql[2][8];
#pragma unroll
    for (int j = 0; j < 2; j++) {
        int s = warp + 32 * j;
        qtv[j] = qt[s]; qbv[j] = qb[s];
#pragma unroll
        for (int m = 0; m < 8; m++) ql[j][m] = ql1[s * 8 + m];
    }
    const float scale = 0.08838834764831845f;  // 128^-0.5
#pragma unroll
    for (int i = 0; i < 4; i++) {
        int z = lane + 32 * i;
        int ktv = kt[z], kbv = kb[z];
        int4 lpa = *(const int4*)&kl[z * 20 + 0];   // {l1_0,l2_0,l1_1,l2_1}
        int4 lpb = *(const int4*)&kl[z * 20 + 4];
        int4 lpc = *(const int4*)&kl[z * 20 + 8];
        int4 lpd = *(const int4*)&kl[z * 20 + 12];
#pragma unroll
        for (int j = 0; j < 2; j++) {
            float val = acc[j][i] * scale;
            if (qtv[j] < ktv)  val = MNEG;
            if (qtv[j] == ktv) val = -10000.f;
            if (qbv[j] != kbv) val = MNEG;
            int cnt = 0;
            cnt += (ql[j][0] == lpa.x) + (ql[j][0] == lpa.y);
            cnt += (ql[j][1] == lpa.z) + (ql[j][1] == lpa.w);
            cnt += (ql[j][2] == lpb.x) + (ql[j][2] == lpb.y);
            cnt += (ql[j][3] == lpb.z) + (ql[j][3] == lpb.w);
            cnt += (ql[j][4] == lpc.x) + (ql[j][4] == lpc.y);
            cnt += (ql[j][5] == lpc.z) + (ql[j][5] == lpc.w);
            cnt += (ql[j][6] == lpd.x) + (ql[j][6] == lpd.y);
            cnt += (ql[j][7] == lpd.z) + (ql[j][7] == lpd.w);
            val -= __logf((float)cnt + 1e-9f);
            acc[j][i] = val;
        }
    }

    // ---- per-row softmax via warp shuffles; probs overwrite qs rows ----
#pragma unroll
    for (int j = 0; j < 2; j++) {
        float m = fmaxf(fmaxf(acc[j][0], acc[j][1]), fmaxf(acc[j][2], acc[j][3]));
#pragma unroll
        for (int o = 16; o > 0; o >>= 1) m = fmaxf(m, __shfl_xor_sync(0xffffffffu, m, o));
        float e[4]; float sum = 0.f;
#pragma unroll
        for (int i = 0; i < 4; i++) { e[i] = __expf(acc[j][i] - m); sum += e[i]; }
#pragma unroll
        for (int o = 16; o > 0; o >>= 1) sum += __shfl_xor_sync(0xffffffffu, sum, o);
        int s = warp + 32 * j;
        if (lane == 0) g_slog[b][n * BS + s] = m + __logf(sum);
        float inv = 1.f / sum;
#pragma unroll
        for (int i = 0; i < 4; i++) qs[s * PAD + lane + 32 * i] = e[i] * inv;
    }
    __syncwarp();  // warp-private rows: intra-warp visibility only

    // ---- PV: 2 rows x 4 d-cols, packed f32x2 over d-pairs ----
    ull o2[2][2];
#pragma unroll
    for (int j = 0; j < 2; j++) { o2[j][0] = 0ull; o2[j][1] = 0ull; }
    int dd = lane * 4;
#pragma unroll 4
    for (int z0 = 0; z0 < 128; z0 += 4) {
        ulonglong2 vv0 = *(const ulonglong2*)(vs + (z0 + 0) * PAD + dd);
        ulonglong2 vv1 = *(const ulonglong2*)(vs + (z0 + 1) * PAD + dd);
        ulonglong2 vv2 = *(const ulonglong2*)(vs + (z0 + 2) * PAD + dd);
        ulonglong2 vv3 = *(const ulonglong2*)(vs + (z0 + 3) * PAD + dd);
#pragma unroll
        for (int j = 0; j < 2; j++) {
            float4 p4 = *(const float4*)(qs + (warp + 32 * j) * PAD + z0);  // broadcast
            ull pp;
            pp = pack2(p4.x, p4.x); fma2(o2[j][0], pp, vv0.x); fma2(o2[j][1], pp, vv0.y);
            pp = pack2(p4.y, p4.y); fma2(o2[j][0], pp, vv1.x); fma2(o2[j][1], pp, vv1.y);
            pp = pack2(p4.z, p4.z); fma2(o2[j][0], pp, vv2.x); fma2(o2[j][1], pp, vv2.y);
            pp = pack2(p4.w, p4.w); fma2(o2[j][0], pp, vv3.x); fma2(o2[j][1], pp, vv3.y);
        }
    }
#pragma unroll
    for (int j = 0; j < 2; j++) {
        int s = warp + 32 * j;
        float2 a = unpack2(o2[j][0]);
        float2 c = unpack2(o2[j][1]);
        *(float4*)(&g_so[b][n * BS + s][dd]) = make_float4(a.x, a.y, c.x, c.y);
    }
}

// cross-hash-round combine. grid (SL, B), block 128 (one thread per dim)
__global__ void k_combine(float* __restrict__ out) {
    int t = blockIdx.x, b = blockIdx.y;
    int d = threadIdx.x;
    int p[NH];
    float l[NH];
    float m = MNEG;
#pragma unroll
    for (int h = 0; h < NH; h++) {
        p[h] = g_undo[b][h * SL + t];
        l[h] = g_slog[b][p[h]];
        m = fmaxf(m, l[h]);
    }
    float sum = 0.f;
#pragma unroll
    for (int h = 0; h < NH; h++) { l[h] = __expf(l[h] - m); sum += l[h]; }
    float inv = 1.f / sum;
    float acc = 0.f;
#pragma unroll
    for (int h = 0; h < NH; h++) acc += l[h] * inv * g_so[b][p[h]][d];
    out[((size_t)b * SL + t) * D + d] = acc;
}

// ---------------- launch ----------------------------------------------------
extern "C" void kernel_launch(void* const* d_in, const int* in_sizes, int n_in,
                              void* d_out, int out_size) {
    (void)in_sizes; (void)n_in; (void)out_size;
    const float* qk  = (const float*)d_in[0];
    const float* v   = (const float*)d_in[1];
    const float* rot = (const float*)d_in[2];
    float* out = (float*)d_out;

    // floats: (64+128+128)*PAD ; ints: 64+64+128+128+512+128*20 = 3456
    const int smem_bytes = (320 * PAD) * 4 + 3456 * 4;  // 182,784 B
    cudaFuncSetAttribute(k_attn, cudaFuncAttributeMaxDynamicSharedMemorySize, smem_bytes);

    k_zero_hist<<<B, NC>>>();
    k_buckets<<<dim3(SL / 256, NH, B), 256>>>(qk, rot);
    k_prefix<<<B, NC>>>();
    k_scatter<<<dim3(NC, B), 128>>>();
    k_loc<<<(B * NSL) / 256, 256>>>();
    k_attn<<<dim3(NC, B), 1024, smem_bytes>>>(qk, v);
    k_combine<<<dim3(SL, B), 128>>>(out);
}

// round 8
// speedup vs baseline: 1.1871x; 1.1871x over previous
#include <cuda_runtime.h>
#include <math.h>

#define B 8
#define SL 4096
#define D 128
#define NH 8
#define NB 64       // buckets per hash
#define NC 512      // n_chunks = NH * NB
#define BS 64       // bucket/chunk size
#define NSL (NH*SL) // 32768
#define PAD 132     // smem row stride (floats); %32==4 -> conflict-free rows & cols

#define MNEG (-3.402823466e38f)

typedef unsigned long long ull;

// packed 2x fp32 fma (Blackwell f32x2 pipe; PTX-only)
__device__ __forceinline__ void fma2(ull& d, ull a, ull b) {
    asm("fma.rn.f32x2 %0, %1, %2, %0;" : "+l"(d) : "l"(a), "l"(b));
}
__device__ __forceinline__ ull pack2(float lo, float hi) {
    ull r; asm("mov.b64 %0, {%1, %2};" : "=l"(r) : "f"(lo), "f"(hi)); return r;
}
__device__ __forceinline__ float2 unpack2(ull v) {
    float2 r; asm("mov.b64 {%0, %1}, %2;" : "=f"(r.x), "=f"(r.y) : "l"(v)); return r;
}

// ---------------- scratch (device globals; no runtime allocation) ----------
__device__ int   g_buckets[B][NH][SL];   // bucket incl. h*NB offset
__device__ int   g_hist[B][NC];
__device__ int   g_boff[B][NC];
__device__ int   g_sticker[B][NSL];      // sorted tickers
__device__ int   g_undo[B][NSL];         // ticker -> sorted pos
__device__ int   g_loc1[B][NH][SL];
__device__ int   g_loc2[B][NH][SL];
__device__ float g_so[B][NSL][D];        // sorted attention output
__device__ float g_slog[B][NSL];         // sorted lse

// ---------------- kernels --------------------------------------------------
__global__ void k_zero_hist() {
    g_hist[blockIdx.x][threadIdx.x] = 0;
}

// buckets + histogram. grid (SL/256, NH, B), block 256.
__global__ void k_buckets(const float* __restrict__ qk, const float* __restrict__ rot) {
    __shared__ float rs[32 * 32];      // d-tile (32) x n (32)
    __shared__ float qt_[256 * 33];    // tokens x d-tile, stride 33
    int b = blockIdx.z, h = blockIdx.y;
    int tid = threadIdx.x;
    int s0 = blockIdx.x * 256;

    ull acc2[16];
#pragma unroll
    for (int n = 0; n < 16; n++) acc2[n] = 0ull;

    for (int d0 = 0; d0 < 128; d0 += 32) {
        for (int i = tid; i < 32 * 32; i += 256) {
            int dd = i >> 5, nn = i & 31;
            rs[i] = rot[((size_t)(d0 + dd) * NH + h) * 32 + nn];
        }
        for (int i = tid; i < 256 * 32; i += 256) {
            int r = i >> 5, c = i & 31;
            qt_[r * 33 + c] = qk[((size_t)b * SL + s0 + r) * D + d0 + c];
        }
        __syncthreads();
#pragma unroll 4
        for (int dd = 0; dd < 32; dd++) {
            float qv = qt_[tid * 33 + dd];
            ull qq = pack2(qv, qv);
            const ull* r2 = (const ull*)&rs[dd * 32];
#pragma unroll
            for (int n = 0; n < 16; n++) fma2(acc2[n], qq, r2[n]);
        }
        __syncthreads();
    }
    float acc[32];
#pragma unroll
    for (int n = 0; n < 16; n++) {
        float2 p = unpack2(acc2[n]);
        acc[2 * n] = p.x; acc[2 * n + 1] = p.y;
    }
    // argmax over [acc, -acc], first-max-wins (matches jnp.argmax)
    float best = acc[0]; int idx = 0;
#pragma unroll
    for (int n = 1; n < 32; n++) if (acc[n] > best) { best = acc[n]; idx = n; }
#pragma unroll
    for (int n = 0; n < 32; n++) if (-acc[n] > best) { best = -acc[n]; idx = 32 + n; }
    int s = s0 + tid;
    int bucket = idx + h * NB;
    g_buckets[b][h][s] = bucket;
    atomicAdd(&g_hist[b][bucket], 1);
}

// exclusive scan of 512 bins per batch. grid B, block NC. Hillis-Steele.
__global__ void k_prefix() {
    __shared__ int sh[NC];
    int b = blockIdx.x, tid = threadIdx.x;
    int v = g_hist[b][tid];
    sh[tid] = v;
    __syncthreads();
#pragma unroll
    for (int off = 1; off < NC; off <<= 1) {
        int x = (tid >= off) ? sh[tid - off] : 0;
        __syncthreads();
        sh[tid] += x;
        __syncthreads();
    }
    g_boff[b][tid] = sh[tid] - v;   // exclusive
}

// stable counting-sort scatter: 4 warps per bucket, two-pass (count, scatter).
// grid (NC, B), block 128
__global__ void k_scatter() {
    int bk = blockIdx.x, b = blockIdx.y;
    int h = bk >> 6;
    int warp = threadIdx.x >> 5, lane = threadIdx.x & 31;
    const int* bb = &g_buckets[b][h][0];
    int t0 = warp * (SL / 4);

    __shared__ int wc[4];
    int cnt = 0;
    for (int base = 0; base < SL / 4; base += 32) {
        bool m = (bb[t0 + base + lane] == bk);
        cnt += __popc(__ballot_sync(0xffffffffu, m));
    }
    if (lane == 0) wc[warp] = cnt;
    __syncthreads();

    int pos = g_boff[b][bk];
#pragma unroll
    for (int w = 0; w < 4; w++) if (w < warp) pos += wc[w];

    for (int base = 0; base < SL / 4; base += 32) {
        int t = t0 + base + lane;
        bool m = (bb[t] == bk);
        unsigned bal = __ballot_sync(0xffffffffu, m);
        if (m) {
            int r = __popc(bal & ((1u << lane) - 1));
            int j = h * SL + t;
            g_sticker[b][pos + r] = j;
            g_undo[b][j] = pos + r;
        }
        pos += __popc(bal);
    }
}

// duplicate-detection location codes. grid (B*NSL/256), block 256
__global__ void k_loc() {
    int idx = blockIdx.x * 256 + threadIdx.x;
    int b = idx / NSL, r = idx % NSL;
    int h = r >> 12, t = r & (SL - 1);
    int chunk = g_undo[b][r] >> 6;
    int bucket = g_buckets[b][h][t];
    g_loc1[b][h][t] = bucket * NC + chunk;
    g_loc2[b][h][t] = bucket * NC + ((chunk + 1) & (NC - 1));
}

// chunked attention. grid (NC, B), block 512, dynamic smem, 2 blocks/SM.
// 16 warps; QK: warp w owns query rows {w, w+16, w+32, w+48}.
// One 128-row buffer holds K during QK, then V during PV (re-gathered).
// PV: warp pair (2u,2u+1) owns rows {u, u+8, ..., u+56}; warp 2u d[0:64), 2u+1 d[64:128).
extern __shared__ float smem[];
__global__ void __launch_bounds__(512, 2)
k_attn(const float* __restrict__ qk, const float* __restrict__ v) {
    int n = blockIdx.x, b = blockIdx.y;
    int tid = threadIdx.x;
    int warp = tid >> 5, lane = tid & 31;

    float* qs = smem;              // 64*PAD  (q rows; reused as probs)
    float* kv = qs + 64 * PAD;     // 128*PAD (K in phase 1, V in phase 2)
    int* qt = (int*)(kv + 128 * PAD); // 64
    int* qb = qt + 64;                // 64
    int* kt = qb + 64;                // 128
    int* kb = kt + 128;               // 128
    int* ql1 = kb + 128;              // 64*8
    int* kl  = ql1 + 512;             // 128*18 (loc1/loc2 interleaved pairs)

    int prev = (n + NC - 1) & (NC - 1);

    // ---- batched index loads first (full MLP on the dependent gathers) ----
    int tfk[8], tfq[4];
#pragma unroll
    for (int u = 0; u < 8; u++) {
        int z = warp + 16 * u;
        int p = (z < 64) ? (n * BS + z) : (prev * BS + (z - 64));
        tfk[u] = g_sticker[b][p];
    }
#pragma unroll
    for (int u = 0; u < 4; u++)
        tfq[u] = g_sticker[b][n * BS + warp + 16 * u];

    // ---- K rows (z<64 current chunk, z>=64 previous chunk) ----
#pragma unroll
    for (int u = 0; u < 8; u++) {
        int z = warp + 16 * u;
        int t = tfk[u] & (SL - 1), h = tfk[u] >> 12;
        const float* src = qk + ((size_t)b * SL + t) * D;
        float4 x = ((const float4*)src)[lane];
        float ss = x.x * x.x + x.y * x.y + x.z * x.z + x.w * x.w;
#pragma unroll
        for (int o = 16; o > 0; o >>= 1) ss += __shfl_xor_sync(0xffffffffu, ss, o);
        float inv = rsqrtf(fmaxf(ss, 1e-24f));
        ((float4*)(kv + z * PAD))[lane] = make_float4(x.x * inv, x.y * inv, x.z * inv, x.w * inv);
        if (lane == 0) { kt[z] = t; kb[z] = g_buckets[b][h][t]; }
        if (lane < 8)       kl[z * 18 + 2 * lane]           = g_loc1[b][lane][t];
        else if (lane < 16) kl[z * 18 + 2 * (lane - 8) + 1] = g_loc2[b][lane - 8][t];
    }
    // ---- q rows ----
#pragma unroll
    for (int u = 0; u < 4; u++) {
        int s = warp + 16 * u;
        int t = tfq[u] & (SL - 1), h = tfq[u] >> 12;
        ((float4*)(qs + s * PAD))[lane] = ((const float4*)(qk + ((size_t)b * SL + t) * D))[lane];
        if (lane == 0) { qt[s] = t; qb[s] = g_buckets[b][h][t]; }
        if (lane < 8) ql1[s * 8 + lane] = g_loc1[b][lane][t];
    }
    __syncthreads();

    // ---- QK^T: 4 rows x 4 z tile, packed f32x2 over even/odd d ----
    ull acc2[4][4];
#pragma unroll
    for (int j = 0; j < 4; j++)
#pragma unroll
        for (int i = 0; i < 4; i++) acc2[j][i] = 0ull;

#pragma unroll 2
    for (int d = 0; d < 128; d += 4) {
        ulonglong2 kx[4];
#pragma unroll
        for (int i = 0; i < 4; i++)
            kx[i] = *(const ulonglong2*)(kv + (lane + 32 * i) * PAD + d);
#pragma unroll
        for (int j = 0; j < 4; j++) {
            ulonglong2 q2 = *(const ulonglong2*)(qs + (warp + 16 * j) * PAD + d);  // broadcast
#pragma unroll
            for (int i = 0; i < 4; i++) {
                fma2(acc2[j][i], q2.x, kx[i].x);
                fma2(acc2[j][i], q2.y, kx[i].y);
            }
        }
    }
    float acc[4][4];
#pragma unroll
    for (int j = 0; j < 4; j++)
#pragma unroll
        for (int i = 0; i < 4; i++) {
            float2 p = unpack2(acc2[j][i]);
            acc[j][i] = p.x + p.y;
        }

    // ---- masks + dup correction (reference order: causal, self, bucket, dup) ----
    const float scale = 0.08838834764831845f;  // 128^-0.5
#pragma unroll
    for (int j = 0; j < 4; j++) {
        int s = warp + 16 * j;
        int qtv = qt[s], qbv = qb[s];
        int ql[8];
#pragma unroll
        for (int m = 0; m < 8; m++) ql[m] = ql1[s * 8 + m];
#pragma unroll
        for (int i = 0; i < 4; i++) {
            int z = lane + 32 * i;
            float val = acc[j][i] * scale;
            int ktv = kt[z];
            if (qtv < ktv)  val = MNEG;
            if (qtv == ktv) val = -10000.f;
            if (qbv != kb[z]) val = MNEG;
            int cnt = 0;
#pragma unroll
            for (int m = 0; m < 8; m++) {
                int2 lp = *(const int2*)&kl[z * 18 + 2 * m];
                cnt += (ql[m] == lp.x) + (ql[m] == lp.y);
            }
            val -= __logf((float)cnt + 1e-9f);
            acc[j][i] = val;
        }
    }

    // ---- per-row softmax via warp shuffles; probs overwrite own qs rows ----
#pragma unroll
    for (int j = 0; j < 4; j++) {
        float m = fmaxf(fmaxf(acc[j][0], acc[j][1]), fmaxf(acc[j][2], acc[j][3]));
#pragma unroll
        for (int o = 16; o > 0; o >>= 1) m = fmaxf(m, __shfl_xor_sync(0xffffffffu, m, o));
        float e[4]; float sum = 0.f;
#pragma unroll
        for (int i = 0; i < 4; i++) { e[i] = __expf(acc[j][i] - m); sum += e[i]; }
#pragma unroll
        for (int o = 16; o > 0; o >>= 1) sum += __shfl_xor_sync(0xffffffffu, sum, o);
        int s = warp + 16 * j;
        if (lane == 0) g_slog[b][n * BS + s] = m + __logf(sum);
        float inv = 1.f / sum;
#pragma unroll
        for (int i = 0; i < 4; i++) qs[s * PAD + lane + 32 * i] = e[i] * inv;
    }
    __syncthreads();   // all warps done reading K; probs now block-visible

    // ---- phase 2: gather V into the shared buffer ----
#pragma unroll
    for (int u = 0; u < 8; u++) {
        int z = warp + 16 * u;
        int p = (z < 64) ? (n * BS + z) : (prev * BS + (z - 64));
        int t = g_sticker[b][p] & (SL - 1);
        ((float4*)(kv + z * PAD))[lane] = ((const float4*)(v + ((size_t)b * SL + t) * D))[lane];
    }
    __syncthreads();

    // ---- PV: warp pair splits d; 8 rows x 2 d-cols (f32x2) per thread ----
    int prow0 = warp >> 1;                 // pair id: rows prow0 + 8*k
    int dd2 = (warp & 1) * 64 + lane * 2;  // this warp's d-half
    ull o2[8];
#pragma unroll
    for (int k = 0; k < 8; k++) o2[k] = 0ull;

#pragma unroll 2
    for (int z0 = 0; z0 < 128; z0 += 4) {
        ull vv0 = *(const ull*)(kv + (z0 + 0) * PAD + dd2);
        ull vv1 = *(const ull*)(kv + (z0 + 1) * PAD + dd2);
        ull vv2 = *(const ull*)(kv + (z0 + 2) * PAD + dd2);
        ull vv3 = *(const ull*)(kv + (z0 + 3) * PAD + dd2);
#pragma unroll
        for (int k = 0; k < 8; k++) {
            float4 p4 = *(const float4*)(qs + (prow0 + 8 * k) * PAD + z0);  // broadcast
            fma2(o2[k], pack2(p4.x, p4.x), vv0);
            fma2(o2[k], pack2(p4.y, p4.y), vv1);
            fma2(o2[k], pack2(p4.z, p4.z), vv2);
            fma2(o2[k], pack2(p4.w, p4.w), vv3);
        }
    }
#pragma unroll
    for (int k = 0; k < 8; k++) {
        int s = prow0 + 8 * k;
        float2 a = unpack2(o2[k]);
        *(float2*)(&g_so[b][n * BS + s][dd2]) = a;
    }
}

// cross-hash-round combine. grid (SL, B), block 128 (one thread per dim)
__global__ void k_combine(float* __restrict__ out) {
    int t = blockIdx.x, b = blockIdx.y;
    int d = threadIdx.x;
    int p[NH];
    float l[NH];
    float m = MNEG;
#pragma unroll
    for (int h = 0; h < NH; h++) {
        p[h] = g_undo[b][h * SL + t];
        l[h] = g_slog[b][p[h]];
        m = fmaxf(m, l[h]);
    }
    float sum = 0.f;
#pragma unroll
    for (int h = 0; h < NH; h++) { l[h] = __expf(l[h] - m); sum += l[h]; }
    float inv = 1.f / sum;
    float acc = 0.f;
#pragma unroll
    for (int h = 0; h < NH; h++) acc += l[h] * inv * g_so[b][p[h]][d];
    out[((size_t)b * SL + t) * D + d] = acc;
}

// ---------------- launch ----------------------------------------------------
extern "C" void kernel_launch(void* const* d_in, const int* in_sizes, int n_in,
                              void* d_out, int out_size) {
    (void)in_sizes; (void)n_in; (void)out_size;
    const float* qk  = (const float*)d_in[0];
    const float* v   = (const float*)d_in[1];
    const float* rot = (const float*)d_in[2];
    float* out = (float*)d_out;

    // floats: (64+128)*PAD ; ints: 64+64+128+128+512+128*18 = 3200
    const int smem_bytes = (192 * PAD) * 4 + 3200 * 4;  // 114,176 B -> 2 blocks/SM
    cudaFuncSetAttribute(k_attn, cudaFuncAttributeMaxDynamicSharedMemorySize, smem_bytes);

    k_zero_hist<<<B, NC>>>();
    k_buckets<<<dim3(SL / 256, NH, B), 256>>>(qk, rot);
    k_prefix<<<B, NC>>>();
    k_scatter<<<dim3(NC, B), 128>>>();
    k_loc<<<(B * NSL) / 256, 256>>>();
    k_attn<<<dim3(NC, B), 512, smem_bytes>>>(qk, v);
    k_combine<<<dim3(SL, B), 128>>>(out);
}